// round 4
// baseline (speedup 1.0000x reference)
#include <cuda_runtime.h>
#include <cuda_bf16.h>

#define BB 16384
#define DD 256
constexpr int BD = BB * DD;
constexpr float GAMMA_ = 0.01f;
constexpr float HG = 0.005f;           // gamma/2
constexpr int SW = 132;                // smem row stride in 32-bit words (264 bf16)
constexpr int MT = 128;                // rows per CTA
constexpr size_t SME = (size_t)(256 * SW + MT * SW) * 4;  // 202752 bytes

// ---------------- scratch state (device globals; no allocation) ----------------
__device__ float g_z[BD];
__device__ float g_v[BD];
__device__ float g_vh[BD];
__device__ float g_p[BD];
__device__ float g_q[BD];
__device__ float g_t[BD];
__device__ float g_C[BD];
__device__ __nv_bfloat16 g_Wb[DD * DD];   // B[n][k] = W[n][k]   (x @ W^T form: gradients)
__device__ __nv_bfloat16 g_Wtb[DD * DD];  // B[n][k] = W[k][n]   (x @ W form: a, c)

// ---------------- helpers ----------------
__device__ __forceinline__ void spsig(float x, float& sp, float& sg) {
    float ax = fabsf(x);
    float e = __expf(-ax);
    float l = __logf(1.f + e);
    sp = fmaxf(x, 0.f) + l;
    sg = (x >= 0.f) ? __fdividef(1.f, 1.f + e) : __fdividef(e, 1.f + e);
}
__device__ __forceinline__ float softplus_f(float x) {
    float ax = fabsf(x);
    return fmaxf(x, 0.f) + __logf(1.f + __expf(-ax));
}

__device__ __forceinline__ void mma_16816(float* d, const unsigned* a, const unsigned* b) {
    asm volatile(
        "mma.sync.aligned.m16n8k16.row.col.f32.bf16.bf16.f32 "
        "{%0,%1,%2,%3}, {%4,%5,%6,%7}, {%8,%9}, {%0,%1,%2,%3};\n"
        : "+f"(d[0]), "+f"(d[1]), "+f"(d[2]), "+f"(d[3])
        : "r"(a[0]), "r"(a[1]), "r"(a[2]), "r"(a[3]), "r"(b[0]), "r"(b[1]));
}

// EPI: 0=PQ (p,q from a=acc+bias)
//      1=VSTEP (O0 = E0 - HG*acc)                        [E0 = previous vh iterate]
//      2=T   (t from c=acc+bias)
//      3=CADD (O0 = HG*(E0/E1)*E2 - GAMMA*acc)           [E0=p,E1=q,E2=vh]
//      4=ZSTEP (O0 = E2 + E0 + HG*softplus(acc+bias)*E1) [E0=Cadd,E1=vh,E2=z]
template <int EPI>
__device__ __forceinline__ void epi_pair(float a0, float a1, int row, int col,
                                         const float* __restrict__ bias,
                                         const float* __restrict__ E0, const float* __restrict__ E1,
                                         const float* __restrict__ E2,
                                         float* __restrict__ O0, float* __restrict__ O1) {
    const int off = row * DD + col;
    if (EPI == 0 || EPI == 2 || EPI == 4) {
        float2 bb = *(const float2*)(bias + col);
        a0 += bb.x; a1 += bb.y;
    }
    if (EPI == 0 || EPI == 2) {
        float sp0, sg0, sp1, sg1;
        spsig(a0, sp0, sg0);
        spsig(a1, sp1, sg1);
        float p0 = 0.5f * sg0, p1 = 0.5f * sg1;
        float q0 = __fdividef(p0, sp0), q1 = __fdividef(p1, sp1);
        if (EPI == 0) {
            *(float2*)(O0 + off) = make_float2(p0, p1);
            *(float2*)(O1 + off) = make_float2(q0, q1);
        } else {
            *(float2*)(O0 + off) = make_float2(q0, q1);
        }
    } else if (EPI == 1) {
        float2 vb = *(const float2*)(E0 + off);
        *(float2*)(O0 + off) = make_float2(vb.x - HG * a0, vb.y - HG * a1);
    } else if (EPI == 3) {
        float2 pp = *(const float2*)(E0 + off);
        float2 qq = *(const float2*)(E1 + off);
        float2 vv = *(const float2*)(E2 + off);
        float s0 = __fdividef(pp.x, qq.x), s1 = __fdividef(pp.y, qq.y);  // = softplus(a_old)
        *(float2*)(O0 + off) = make_float2(HG * s0 * vv.x - GAMMA_ * a0,
                                           HG * s1 * vv.y - GAMMA_ * a1);
    } else if (EPI == 4) {
        float2 CC = *(const float2*)(E0 + off);
        float2 vv = *(const float2*)(E1 + off);
        float2 zz = *(const float2*)(E2 + off);
        float sp0 = softplus_f(a0), sp1 = softplus_f(a1);
        *(float2*)(O0 + off) = make_float2(zz.x + CC.x + HG * sp0 * vv.x,
                                           zz.y + CC.y + HG * sp1 * vv.y);
    }
}

// ---------------- fused GEMM kernel ----------------
// D[16384,256] = A[16384,256] @ Bsm^T  where Bsm[n][k] is one of g_Wb / g_Wtb.
// PRO: 0 -> A = A0 (fp32); 1 -> A = A0*A2*A2 - A1  (r = p*vh^2 - q)
template <int PRO, int EPI>
__global__ __launch_bounds__(256, 1) void k_gemm(
    const float* __restrict__ A0, const float* __restrict__ A1, const float* __restrict__ A2,
    const __nv_bfloat16* __restrict__ Bg, const float* __restrict__ bias,
    const float* __restrict__ E0, const float* __restrict__ E1,
    const float* __restrict__ E2,
    float* __restrict__ O0, float* __restrict__ O1) {
    extern __shared__ unsigned sh[];
    unsigned* shB = sh;                 // 256 x 132 words
    unsigned* shA = sh + 256 * SW;      // 128 x 132 words
    const int tid = threadIdx.x;
    const int row0 = blockIdx.x * MT;

    // load B (bf16 row-major [n][k], 256x256) into padded smem
    {
        const uint4* Bq = (const uint4*)Bg;
#pragma unroll
        for (int it = 0; it < 32; ++it) {
            int idx = it * 256 + tid;
            int n = idx >> 5, c4 = idx & 31;
            uint4 u = Bq[idx];
            unsigned* d = &shB[n * SW + c4 * 4];
            d[0] = u.x; d[1] = u.y; d[2] = u.z; d[3] = u.w;
        }
    }
    // load/compute A tile (128x256 fp32 -> bf16) into padded smem
    {
#pragma unroll
        for (int it = 0; it < 64; ++it) {
            int idx = it * 256 + tid;
            int row = idx >> 7, c2 = idx & 127;
            int go = (row0 + row) * (DD / 2) + c2;
            float2 x;
            if (PRO == 0) {
                x = ((const float2*)A0)[go];
            } else {
                float2 pp = ((const float2*)A0)[go];
                float2 qq = ((const float2*)A1)[go];
                float2 vv = ((const float2*)A2)[go];
                x.x = pp.x * vv.x * vv.x - qq.x;
                x.y = pp.y * vv.y * vv.y - qq.y;
            }
            __nv_bfloat162 h = __float22bfloat162_rn(x);
            shA[row * SW + c2] = *reinterpret_cast<unsigned*>(&h);
        }
    }
    __syncthreads();

    const int lane = tid & 31, warp = tid >> 5;
    const int wM = warp >> 2, wN = warp & 3;   // 2 x 4 warp grid: 64 rows x 64 cols per warp
    const int g = lane >> 2, qd = lane & 3;

    float acc[4][8][4];
#pragma unroll
    for (int mt = 0; mt < 4; ++mt)
#pragma unroll
        for (int nt = 0; nt < 8; ++nt)
#pragma unroll
            for (int i = 0; i < 4; ++i) acc[mt][nt][i] = 0.f;

#pragma unroll 1
    for (int kt = 0; kt < 16; ++kt) {
        const int kw = kt * 8 + qd;
        unsigned aF[4][4];
#pragma unroll
        for (int mt = 0; mt < 4; ++mt) {
            int r = wM * 64 + mt * 16 + g;
            aF[mt][0] = shA[r * SW + kw];
            aF[mt][1] = shA[(r + 8) * SW + kw];
            aF[mt][2] = shA[r * SW + kw + 4];
            aF[mt][3] = shA[(r + 8) * SW + kw + 4];
        }
        unsigned bF[8][2];
#pragma unroll
        for (int nt = 0; nt < 8; ++nt) {
            int n = wN * 64 + nt * 8 + g;
            bF[nt][0] = shB[n * SW + kw];
            bF[nt][1] = shB[n * SW + kw + 4];
        }
#pragma unroll
        for (int mt = 0; mt < 4; ++mt)
#pragma unroll
            for (int nt = 0; nt < 8; ++nt) mma_16816(acc[mt][nt], aF[mt], bF[nt]);
    }

    // epilogue
#pragma unroll
    for (int mt = 0; mt < 4; ++mt) {
        int ra = row0 + wM * 64 + mt * 16 + g;
#pragma unroll
        for (int nt = 0; nt < 8; ++nt) {
            int col = wN * 64 + nt * 8 + qd * 2;
            epi_pair<EPI>(acc[mt][nt][0], acc[mt][nt][1], ra, col, bias, E0, E1, E2, O0, O1);
            epi_pair<EPI>(acc[mt][nt][2], acc[mt][nt][3], ra + 8, col, bias, E0, E1, E2, O0, O1);
        }
    }
}

// ---------------- small kernels ----------------
__global__ void k_convW(const float* __restrict__ W) {
    int i = blockIdx.x, j = threadIdx.x;
    float w = W[i * DD + j];
    g_Wb[i * DD + j] = __float2bfloat16(w);
    g_Wtb[j * DD + i] = __float2bfloat16(w);
}
__global__ void k_init(const float4* __restrict__ z0, const float4* __restrict__ v0) {
    float4* z = (float4*)g_z;
    float4* v = (float4*)g_v;
    for (int i = blockIdx.x * blockDim.x + threadIdx.x; i < BD / 4; i += gridDim.x * blockDim.x) {
        z[i] = z0[i];
        v[i] = v0[i];
    }
}
__global__ void k_out(float4* __restrict__ out) {
    const float4* z = (const float4*)g_z;
    const float4* v = (const float4*)g_v;
    for (int i = blockIdx.x * blockDim.x + threadIdx.x; i < BD / 4; i += gridDim.x * blockDim.x) {
        out[i] = z[i];
        out[BD / 4 + i] = v[i];
    }
}

// ---------------- launch ----------------
extern "C" void kernel_launch(void* const* d_in, const int* in_sizes, int n_in,
                              void* d_out, int out_size) {
    const float* z0 = (const float*)d_in[0];
    const float* v0 = (const float*)d_in[1];
    const float* W = (const float*)d_in[2];
    const float* bias = (const float*)d_in[3];

    float *z, *v, *vh, *p, *q, *t, *C;
    __nv_bfloat16 *Wb, *Wtb;
    cudaGetSymbolAddress((void**)&z, g_z);
    cudaGetSymbolAddress((void**)&v, g_v);
    cudaGetSymbolAddress((void**)&vh, g_vh);
    cudaGetSymbolAddress((void**)&p, g_p);
    cudaGetSymbolAddress((void**)&q, g_q);
    cudaGetSymbolAddress((void**)&t, g_t);
    cudaGetSymbolAddress((void**)&C, g_C);
    cudaGetSymbolAddress((void**)&Wb, g_Wb);
    cudaGetSymbolAddress((void**)&Wtb, g_Wtb);

    cudaFuncSetAttribute(k_gemm<0, 0>, cudaFuncAttributeMaxDynamicSharedMemorySize, SME);
    cudaFuncSetAttribute(k_gemm<1, 1>, cudaFuncAttributeMaxDynamicSharedMemorySize, SME);
    cudaFuncSetAttribute(k_gemm<0, 2>, cudaFuncAttributeMaxDynamicSharedMemorySize, SME);
    cudaFuncSetAttribute(k_gemm<0, 3>, cudaFuncAttributeMaxDynamicSharedMemorySize, SME);
    cudaFuncSetAttribute(k_gemm<0, 4>, cudaFuncAttributeMaxDynamicSharedMemorySize, SME);

    k_convW<<<DD, DD>>>(W);
    k_init<<<2048, 256>>>((const float4*)z0, (const float4*)v0);

    const int G = BB / MT;  // 128 CTAs
    for (int s = 0; s < 6; ++s) {
        // a = z@W + bias -> p, q
        k_gemm<0, 0><<<G, 256, SME>>>(z, nullptr, nullptr, Wtb, bias,
                                      nullptr, nullptr, nullptr, p, q);
        // v-half iterated map: vh_{k+1} = vh_k - HG * (p*vh_k^2 - q) @ W^T
        for (int i = 0; i < 8; ++i) {
            const float* prev = i ? vh : v;
            k_gemm<1, 1><<<G, 256, SME>>>(p, q, prev, Wb, nullptr,
                                          prev, nullptr, nullptr, vh, nullptr);
        }
        // c = vh@W + bias -> t
        k_gemm<0, 2><<<G, 256, SME>>>(vh, nullptr, nullptr, Wtb, bias,
                                      nullptr, nullptr, nullptr, t, nullptr);
        // Cadd = HG*(p/q)*vh - GAMMA*(t @ W^T)     [per-iteration additive constant]
        k_gemm<0, 3><<<G, 256, SME>>>(t, nullptr, nullptr, Wb, nullptr,
                                      p, q, vh, C, nullptr);
        // z iterated map: z_{k+1} = z_k + Cadd + HG*softplus(z_k@W+bias)*vh  (in-place)
        for (int i = 0; i < 8; ++i)
            k_gemm<0, 4><<<G, 256, SME>>>(z, nullptr, nullptr, Wtb, bias,
                                          C, vh, z, z, nullptr);
        // p,q from z_new
        k_gemm<0, 0><<<G, 256, SME>>>(z, nullptr, nullptr, Wtb, bias,
                                      nullptr, nullptr, nullptr, p, q);
        // v_new = vh - HG * (p*vh^2 - q) @ W^T
        k_gemm<1, 1><<<G, 256, SME>>>(p, q, vh, Wb, nullptr,
                                      vh, nullptr, nullptr, v, nullptr);
    }
    k_out<<<2048, 256>>>((float4*)d_out);
}

// round 6
// speedup vs baseline: 1.0493x; 1.0493x over previous
#include <cuda_runtime.h>
#include <cuda_bf16.h>

#define BB 16384
#define DD 256
constexpr int BD = BB * DD;
constexpr float GAMMA_ = 0.01f;
constexpr float HG = 0.005f;          // gamma/2
constexpr int SW = 132;               // smem row stride in 32-bit words (264 bf16)
constexpr int MT = 128;               // rows per CTA
constexpr int NTH = 512;              // threads per CTA (16 warps)
constexpr int W_WORDS = DD * SW;      // 33792 words  (135168 B)
constexpr int A_WORDS = MT * SW;      // 16896 words  (67584 B)
constexpr size_t SME = (size_t)(W_WORDS + A_WORDS + DD) * 4;  // 203776 B

// ---------------- persistent state (device globals; no allocation) ----------------
__device__ float g_z[BD];
__device__ float g_v[BD];
__device__ float g_vh[BD];
__device__ float g_p[BD];
__device__ float g_q[BD];
__device__ float g_t[BD];
__device__ float g_C[BD];

// ---------------- helpers ----------------
__device__ __forceinline__ void spsig(float x, float& sp, float& sg) {
    float ax = fabsf(x);
    float e = __expf(-ax);
    float l = __logf(1.f + e);
    sp = fmaxf(x, 0.f) + l;
    sg = (x >= 0.f) ? __fdividef(1.f, 1.f + e) : __fdividef(e, 1.f + e);
}
__device__ __forceinline__ float softplus_f(float x) {
    float ax = fabsf(x);
    return fmaxf(x, 0.f) + __logf(1.f + __expf(-ax));
}

__device__ __forceinline__ void mma_16816(float* d, const unsigned* a, const unsigned* b) {
    asm volatile(
        "mma.sync.aligned.m16n8k16.row.col.f32.bf16.bf16.f32 "
        "{%0,%1,%2,%3}, {%4,%5,%6,%7}, {%8,%9}, {%0,%1,%2,%3};\n"
        : "+f"(d[0]), "+f"(d[1]), "+f"(d[2]), "+f"(d[3])
        : "r"(a[0]), "r"(a[1]), "r"(a[2]), "r"(a[3]), "r"(b[0]), "r"(b[1]));
}

// transposed ldmatrix: 4 8x8 b16 tiles -> 4 regs (b-fragments for 2 n-tiles at one kt)
__device__ __forceinline__ void ldsm_t4(unsigned& r0, unsigned& r1, unsigned& r2, unsigned& r3,
                                        unsigned addr) {
    asm volatile("ldmatrix.sync.aligned.m8n8.x4.trans.shared.b16 {%0,%1,%2,%3}, [%4];"
                 : "=r"(r0), "=r"(r1), "=r"(r2), "=r"(r3)
                 : "r"(addr));
}

// EPI: 0=PQ   (p,q from a=acc+bias)                         -> O0=p, O1=q
//      1=VSTEP(O0 = E0 - HG*acc)                            [E0 = prev vh (or v)]
//      2=T    (t from c=acc+bias)                           -> O0=t
//      3=CADD (O0 = HG*(E0/E1)*E2 - GAMMA*acc)              [E0=p,E1=q,E2=vh]
//      4=ZSTEP(O0 = E2 + E0 + HG*softplus(acc+bias)*E1)     [E0=Cadd,E1=vh,E2=z]
template <int EPI>
__device__ __forceinline__ void epi_pair(float a0, float a1, int row, int col,
                                         const float* __restrict__ sbias,
                                         const float* __restrict__ E0, const float* __restrict__ E1,
                                         const float* __restrict__ E2,
                                         float* __restrict__ O0, float* __restrict__ O1) {
    const int off = row * DD + col;
    if (EPI == 0 || EPI == 2 || EPI == 4) {
        a0 += sbias[col];
        a1 += sbias[col + 1];
    }
    if (EPI == 0 || EPI == 2) {
        float sp0, sg0, sp1, sg1;
        spsig(a0, sp0, sg0);
        spsig(a1, sp1, sg1);
        float p0 = 0.5f * sg0, p1 = 0.5f * sg1;
        float q0 = __fdividef(p0, sp0), q1 = __fdividef(p1, sp1);
        if (EPI == 0) {
            *(float2*)(O0 + off) = make_float2(p0, p1);
            *(float2*)(O1 + off) = make_float2(q0, q1);
        } else {
            *(float2*)(O0 + off) = make_float2(q0, q1);
        }
    } else if (EPI == 1) {
        float2 vb = *(const float2*)(E0 + off);
        *(float2*)(O0 + off) = make_float2(vb.x - HG * a0, vb.y - HG * a1);
    } else if (EPI == 3) {
        float2 pp = *(const float2*)(E0 + off);
        float2 qq = *(const float2*)(E1 + off);
        float2 vv = *(const float2*)(E2 + off);
        float s0 = __fdividef(pp.x, qq.x), s1 = __fdividef(pp.y, qq.y);  // softplus(a_old)
        *(float2*)(O0 + off) = make_float2(HG * s0 * vv.x - GAMMA_ * a0,
                                           HG * s1 * vv.y - GAMMA_ * a1);
    } else if (EPI == 4) {
        float2 CC = *(const float2*)(E0 + off);
        float2 vv = *(const float2*)(E1 + off);
        float2 zz = *(const float2*)(E2 + off);
        float sp0 = softplus_f(a0), sp1 = softplus_f(a1);
        *(float2*)(O0 + off) = make_float2(zz.x + CC.x + HG * sp0 * vv.x,
                                           zz.y + CC.y + HG * sp1 * vv.y);
    }
}

// ---------------- one GEMM phase (prologue -> mma -> epilogue), CTA-local ----------------
// D[row0:+128, :] = A @ B^T  with shW holding bf16 W[i][j] (row-major, stride SW words).
//   BT=false: B[n][k] = W[n][k] (x @ W^T)  -> direct LDS from shW rows n
//   BT=true : B[n][k] = W[k][n] (x @ W)    -> ldmatrix.trans on shW rows k
// PRO: 0 -> A = f32(A0); 1 -> A = A0*A2*A2 - A1   (r = p*vh^2 - q)
template <int PRO, int EPI, bool BT>
__device__ __forceinline__ void phase(
    const unsigned* __restrict__ shW, unsigned* __restrict__ shA,
    const float* __restrict__ sbias, unsigned wbase,
    int row0, int tid,
    const float* __restrict__ A0, const float* __restrict__ A1, const float* __restrict__ A2,
    const float* __restrict__ E0, const float* __restrict__ E1, const float* __restrict__ E2,
    float* __restrict__ O0, float* __restrict__ O1) {
    // ---- prologue: build bf16 A tile (128 x 256) ----
#pragma unroll 4
    for (int it = 0; it < 32; ++it) {
        int idx = it * NTH + tid;
        int row = idx >> 7, c2 = idx & 127;
        int go = (row0 + row) * (DD / 2) + c2;
        float2 x;
        if (PRO == 0) {
            x = ((const float2*)A0)[go];
        } else {
            float2 pp = ((const float2*)A0)[go];
            float2 qq = ((const float2*)A1)[go];
            float2 vv = ((const float2*)A2)[go];
            x.x = pp.x * vv.x * vv.x - qq.x;
            x.y = pp.y * vv.y * vv.y - qq.y;
        }
        __nv_bfloat162 h = __float22bfloat162_rn(x);
        shA[row * SW + c2] = *reinterpret_cast<unsigned*>(&h);
    }
    __syncthreads();

    // ---- mainloop ----
    const int lane = tid & 31, warp = tid >> 5;
    const int wM = warp >> 2, wN = warp & 3;  // 4x4 warps: 32 rows x 64 cols each
    const int g = lane >> 2, qd = lane & 3;
    const int sub = lane >> 3, rr = lane & 7;

    float acc[2][8][4];
#pragma unroll
    for (int mt = 0; mt < 2; ++mt)
#pragma unroll
        for (int nt = 0; nt < 8; ++nt)
#pragma unroll
            for (int i = 0; i < 4; ++i) acc[mt][nt][i] = 0.f;

#pragma unroll 1
    for (int kt = 0; kt < 16; ++kt) {
        const int kw = kt * 8 + qd;
        unsigned aF[2][4];
#pragma unroll
        for (int mt = 0; mt < 2; ++mt) {
            int r = wM * 32 + mt * 16 + g;
            aF[mt][0] = shA[r * SW + kw];
            aF[mt][1] = shA[(r + 8) * SW + kw];
            aF[mt][2] = shA[r * SW + kw + 4];
            aF[mt][3] = shA[(r + 8) * SW + kw + 4];
        }
        unsigned bF[8][2];
        if (!BT) {
#pragma unroll
            for (int nt = 0; nt < 8; ++nt) {
                int n = wN * 64 + nt * 8 + g;
                bF[nt][0] = shW[n * SW + kw];
                bF[nt][1] = shW[n * SW + kw + 4];
            }
        } else {
#pragma unroll
            for (int np = 0; np < 4; ++np) {
                int rowk = kt * 16 + (sub & 1) * 8 + rr;
                int coln = wN * 64 + np * 16 + (sub >> 1) * 8;
                unsigned a = wbase + (unsigned)(rowk * SW * 4 + coln * 2);
                ldsm_t4(bF[2 * np][0], bF[2 * np][1], bF[2 * np + 1][0], bF[2 * np + 1][1], a);
            }
        }
#pragma unroll
        for (int mt = 0; mt < 2; ++mt)
#pragma unroll
            for (int nt = 0; nt < 8; ++nt) mma_16816(acc[mt][nt], aF[mt], bF[nt]);
    }

    // ---- epilogue ----
#pragma unroll
    for (int mt = 0; mt < 2; ++mt) {
        int ra = row0 + wM * 32 + mt * 16 + g;
#pragma unroll
        for (int nt = 0; nt < 8; ++nt) {
            int col = wN * 64 + nt * 8 + qd * 2;
            epi_pair<EPI>(acc[mt][nt][0], acc[mt][nt][1], ra, col, sbias, E0, E1, E2, O0, O1);
            epi_pair<EPI>(acc[mt][nt][2], acc[mt][nt][3], ra + 8, col, sbias, E0, E1, E2, O0, O1);
        }
    }
    __syncthreads();  // epilogue global writes visible to next prologue; shA safe to overwrite
}

// ---------------- the persistent kernel: full trajectory, one launch ----------------
__global__ __launch_bounds__(NTH, 1) void k_persist(
    const float* __restrict__ z0, const float* __restrict__ v0,
    const float* __restrict__ W, const float* __restrict__ bias,
    float* __restrict__ out) {
    extern __shared__ unsigned sh[];
    unsigned* shW = sh;                        // 256 x 132 words (bf16 W[i][j])
    unsigned* shA = sh + W_WORDS;              // 128 x 132 words
    float* sbias = (float*)(sh + W_WORDS + A_WORDS);
    const int tid = threadIdx.x;
    const int row0 = blockIdx.x * MT;
    const unsigned wbase = (unsigned)__cvta_generic_to_shared(shW);

    // load W (fp32 -> bf16) into smem once
#pragma unroll 4
    for (int it = 0; it < 64; ++it) {
        int idx = it * NTH + tid;  // 0..32767 words
        int i = idx >> 7, j2 = idx & 127;
        float2 wv = ((const float2*)W)[i * 128 + j2];
        __nv_bfloat162 h = __float22bfloat162_rn(wv);
        shW[i * SW + j2] = *reinterpret_cast<unsigned*>(&h);
    }
    if (tid < DD) sbias[tid] = bias[tid];

    // init this CTA's state block
    {
        const int base = row0 * (DD / 4);
#pragma unroll
        for (int it = 0; it < 16; ++it) {
            int idx = base + it * NTH + tid;
            ((float4*)g_z)[idx] = ((const float4*)z0)[idx];
            ((float4*)g_v)[idx] = ((const float4*)v0)[idx];
        }
    }
    __syncthreads();

#pragma unroll 1
    for (int s = 0; s < 6; ++s) {
        // a = z@W + bias -> p, q
        phase<0, 0, true>(shW, shA, sbias, wbase, row0, tid,
                          g_z, nullptr, nullptr, nullptr, nullptr, nullptr, g_p, g_q);
        // v-half iterated map: vh_{k+1} = vh_k - HG * (p*vh_k^2 - q) @ W^T
#pragma unroll 1
        for (int i = 0; i < 8; ++i) {
            const float* prev = i ? g_vh : g_v;
            phase<1, 1, false>(shW, shA, sbias, wbase, row0, tid,
                               g_p, g_q, prev, prev, nullptr, nullptr, g_vh, nullptr);
        }
        // c = vh@W + bias -> t
        phase<0, 2, true>(shW, shA, sbias, wbase, row0, tid,
                          g_vh, nullptr, nullptr, nullptr, nullptr, nullptr, g_t, nullptr);
        // Cadd = HG*(p/q)*vh - GAMMA*(t @ W^T)
        phase<0, 3, false>(shW, shA, sbias, wbase, row0, tid,
                           g_t, nullptr, nullptr, g_p, g_q, g_vh, g_C, nullptr);
        // z iterated map: z_{k+1} = z_k + Cadd + HG*softplus(z_k@W+bias)*vh
#pragma unroll 1
        for (int i = 0; i < 8; ++i)
            phase<0, 4, true>(shW, shA, sbias, wbase, row0, tid,
                              g_z, nullptr, nullptr, g_C, g_vh, g_z, g_z, nullptr);
        // p,q from z_new
        phase<0, 0, true>(shW, shA, sbias, wbase, row0, tid,
                          g_z, nullptr, nullptr, nullptr, nullptr, nullptr, g_p, g_q);
        // v_new = vh - HG * (p*vh^2 - q) @ W^T
        phase<1, 1, false>(shW, shA, sbias, wbase, row0, tid,
                           g_p, g_q, g_vh, g_vh, nullptr, nullptr, g_v, nullptr);
    }

    // write this CTA's output block: out = [z; v]
    {
        const int base = row0 * (DD / 4);
#pragma unroll
        for (int it = 0; it < 16; ++it) {
            int idx = base + it * NTH + tid;
            ((float4*)out)[idx] = ((const float4*)g_z)[idx];
            ((float4*)out)[BD / 4 + idx] = ((const float4*)g_v)[idx];
        }
    }
}

// ---------------- launch ----------------
extern "C" void kernel_launch(void* const* d_in, const int* in_sizes, int n_in,
                              void* d_out, int out_size) {
    const float* z0 = (const float*)d_in[0];
    const float* v0 = (const float*)d_in[1];
    const float* W = (const float*)d_in[2];
    const float* bias = (const float*)d_in[3];

    cudaFuncSetAttribute(k_persist, cudaFuncAttributeMaxDynamicSharedMemorySize, (int)SME);
    k_persist<<<BB / MT, NTH, SME>>>(z0, v0, W, bias, (float*)d_out);
}